// round 7
// baseline (speedup 1.0000x reference)
#include <cuda_runtime.h>

#define NPIX 16384   // 128*128 ROI pixels
#define NS   64      // sensors
#define NT   2030    // time samples
#define NB   64      // batch
#define SNT  (NS*NT) // 129920

// Transposed sinogram: [s][t][b]  (33.3 MB static scratch)
__device__ float g_trans[NS * NT * NB];
__device__ float g_bmax[NB];

// Transpose [b][s*t] -> [s*t][b]; also zero-init g_bmax.
__global__ __launch_bounds__(1024) void transpose_kernel(
    const float* __restrict__ sino)
{
    __shared__ float tile[32][33];
    const int st0 = blockIdx.x * 32;          // 0 .. 129888
    const int b0  = blockIdx.y * 32;          // 0 or 32
    const int tx = threadIdx.x, ty = threadIdx.y;

    if (blockIdx.x == 0 && blockIdx.y == 0 && ty < 2)
        g_bmax[ty * 32 + tx] = 0.0f;

    tile[ty][tx] = sino[(size_t)(b0 + ty) * SNT + st0 + tx];
    __syncthreads();
    g_trans[(size_t)(st0 + ty) * NB + b0 + tx] = tile[tx][ty];
}

// Block = 1024 threads = 32 pixel-warps (32 contiguous pixels).
// Gather role: warp = pixel, lane = 2 batches (float2) -> dense 256B gather.
// Store role (after smem exchange): warp = 2 batches, lane = pixel -> 128B STG.
__global__ __launch_bounds__(1024) void das_kernel(
    const float* __restrict__ wts,    // [NPIX][NS]
    const int*   __restrict__ tidx,   // [NPIX][NS]
    float*       __restrict__ out)    // [NB*NPIX das | NB*NS*NPIX pixel_interp]
{
    __shared__ int   sm_off[32][64];  // fused (s*NT+t)*NB offsets
    __shared__ float sm_w  [32][64];
    __shared__ float ex[2][32][66];   // exchange, pitch 66 (conflict-free)

    const int tid = threadIdx.x;
    const int l   = tid & 31;
    const int w   = tid >> 5;               // warp id: gather pixel / store b-pair
    const int px0 = blockIdx.x * 32;

    // ---- preload geometry for this block's 32 pixels, all 64 sensors ----
    {
        const int px = tid >> 6;             // 0..15 (two passes)
        const int s  = tid & 63;
        #pragma unroll
        for (int h = 0; h < 2; ++h) {
            const int p = px + h * 16;
            int   t = tidx[(px0 + p) * NS + s];
            float v = wts [(px0 + p) * NS + s];
            v = (t >= 0 && t < NT) ? v : 0.0f;
            t = min(max(t, 0), NT - 1);
            sm_off[p][s] = (s * NT + t) * NB;
            sm_w  [p][s] = v;
        }
    }
    __syncthreads();

    float* __restrict__ pi = out + NB * NPIX;
    float2 acc = make_float2(0.0f, 0.0f);

    for (int s = 0; s < NS; ++s) {
        const int   off = sm_off[w][s];      // broadcast LDS
        const float wt  = sm_w  [w][s];

        // dense gather: 64 batches of (pixel w, sensor s) in 2 aligned lines
        float2 v = __ldg(reinterpret_cast<const float2*>(g_trans + off) + l);
        v.x *= wt; v.y *= wt;
        acc.x += v.x; acc.y += v.y;

        const int p = s & 1;
        *reinterpret_cast<float2*>(&ex[p][w][2 * l]) = v;      // STS.64, cf
        __syncthreads();

        float2 u = *reinterpret_cast<const float2*>(&ex[p][l][2 * w]);  // LDS.64, cf
        const size_t o0 = ((size_t)(2 * w) * NS + s) * NPIX + px0 + l;
        __stcs(pi + o0, u.x);                                  // 128B coalesced
        __stcs(pi + o0 + (size_t)NS * NPIX, u.y);
    }

    // ---- das: exchange acc, relu, store, per-batch max ----
    __syncthreads();
    *reinterpret_cast<float2*>(&ex[0][w][2 * l]) = acc;
    __syncthreads();
    float2 a = *reinterpret_cast<const float2*>(&ex[0][l][2 * w]);
    a.x = fmaxf(a.x, 0.0f);
    a.y = fmaxf(a.y, 0.0f);
    __stcs(out + (size_t)(2 * w)     * NPIX + px0 + l, a.x);
    __stcs(out + (size_t)(2 * w + 1) * NPIX + px0 + l, a.y);

    float m0 = a.x, m1 = a.y;
    #pragma unroll
    for (int off = 16; off > 0; off >>= 1) {
        m0 = fmaxf(m0, __shfl_xor_sync(0xffffffffu, m0, off));
        m1 = fmaxf(m1, __shfl_xor_sync(0xffffffffu, m1, off));
    }
    if (l == 0) {
        atomicMax(reinterpret_cast<int*>(&g_bmax[2 * w]),     __float_as_int(m0));
        atomicMax(reinterpret_cast<int*>(&g_bmax[2 * w + 1]), __float_as_int(m1));
    }
}

__global__ __launch_bounds__(256) void norm_kernel(float* __restrict__ out)
{
    int i = blockIdx.x * blockDim.x + threadIdx.x;
    float4* p = reinterpret_cast<float4*>(out);
    float4 v = p[i];
    int b = (i * 4) >> 14;
    float m = g_bmax[b];
    float r = (m > 1e-8f) ? (1.0f / m) : 1.0f;
    v.x *= r; v.y *= r; v.z *= r; v.w *= r;
    p[i] = v;
}

extern "C" void kernel_launch(void* const* d_in, const int* in_sizes, int n_in,
                              void* d_out, int out_size)
{
    const float* sino = (const float*)d_in[0];   // [64,1,64,2030]
    const float* wts  = (const float*)d_in[1];   // [128,128,64]
    const int*   tidx = (const int*)d_in[2];     // [128,128,64]
    float* out = (float*)d_out;

    dim3 tgrid(SNT / 32, NB / 32);                // (4060, 2)
    transpose_kernel<<<tgrid, dim3(32, 32)>>>(sino);

    das_kernel<<<NPIX / 32, 1024>>>(wts, tidx, out);   // 512 blocks

    norm_kernel<<<(NB * NPIX / 4) / 256, 256>>>(out);
}

// round 9
// speedup vs baseline: 1.7391x; 1.7391x over previous
#include <cuda_runtime.h>
#include <cuda_fp16.h>

#define NPIX 16384   // 128*128 ROI pixels
#define NS   64      // sensors
#define NT   2030    // time samples
#define NB   64      // batch
#define SNT  (NS*NT) // 129920

// Transposed fp16 sinogram: [s][t][b]  (16.6 MB -> L2-resident)
__device__ __half g_t16[NS * NT * NB];
__device__ float  g_bmax[NB];

// Transpose+quantize: sino [b][s*t] fp32 -> g_t16 [s*t][b] fp16.
// Block = 512 thr handles a [64 b][64 st] tile. Also zero-inits g_bmax.
__global__ __launch_bounds__(512) void transpose_kernel(
    const float* __restrict__ sino)
{
    __shared__ float tile[64][65];     // [b][st], pitch 65
    const int st0 = blockIdx.x * 64;
    const int tid = threadIdx.x;
    const int l   = tid & 31;
    const int w   = tid >> 5;          // 16 warps

    if (blockIdx.x == 0 && tid < NB) g_bmax[tid] = 0.0f;

    // read: warp w loads b-rows 4w..4w+3, 64 floats each (float2/lane),
    // scalar STS (pitch 65 is odd -> no 8B-aligned smem stores possible)
    #pragma unroll
    for (int k = 0; k < 4; ++k) {
        const int r = w * 4 + k;       // batch index
        float2 v = *reinterpret_cast<const float2*>(
            sino + (size_t)r * SNT + st0 + 2 * l);
        tile[r][2 * l]     = v.x;
        tile[r][2 * l + 1] = v.y;
    }
    __syncthreads();

    // write: warp w emits st-rows 4w..4w+3 as 32 half2 (128B coalesced)
    unsigned int* __restrict__ dst = reinterpret_cast<unsigned int*>(g_t16);
    #pragma unroll
    for (int k = 0; k < 4; ++k) {
        const int st = w * 4 + k;
        __half2 h = __floats2half2_rn(tile[2 * l][st], tile[2 * l + 1][st]);
        dst[(size_t)(st0 + st) * 32 + l] = *reinterpret_cast<unsigned int*>(&h);
    }
}

// Block = 1024 thr = 32 pixel-warps (32 contiguous pixels).
// Gather role: warp = pixel, lane = batch-pair -> ONE 128B line per (pix,s).
// Store role (after conflict-free smem exchange): warp = batch-pair, lane = pixel.
__global__ __launch_bounds__(1024) void das_kernel(
    const float* __restrict__ wts,    // [NPIX][NS]
    const int*   __restrict__ tidx,   // [NPIX][NS]
    float*       __restrict__ out)    // [NB*NPIX das | NB*NS*NPIX pixel_interp]
{
    __shared__ int   sm_off[32][64];        // (s*NT+t)*32 half2-row offsets
    __shared__ float sm_w  [32][64];
    __shared__ float ex[2][2][32][33];      // [buf][plane][w][l], conflict-free

    const int tid = threadIdx.x;
    const int l   = tid & 31;
    const int w   = tid >> 5;
    const int px0 = blockIdx.x * 32;

    // ---- preload geometry: 32 pixels x 64 sensors (coalesced) ----
    {
        const int p = tid >> 6;             // 0..15, two passes
        const int s = tid & 63;
        #pragma unroll
        for (int h = 0; h < 2; ++h) {
            const int pp = p + h * 16;
            int   t = tidx[(px0 + pp) * NS + s];
            float v = wts [(px0 + pp) * NS + s];
            v = (t >= 0 && t < NT) ? v : 0.0f;
            t = min(max(t, 0), NT - 1);
            sm_off[pp][s] = (s * NT + t) * 32;   // uint index of b-row
            sm_w  [pp][s] = v;
        }
    }
    __syncthreads();

    const unsigned int* __restrict__ g2 =
        reinterpret_cast<const unsigned int*>(g_t16);
    float* __restrict__ pi = out + NB * NPIX;
    float2 acc = make_float2(0.0f, 0.0f);

    // prologue: gather s=0 (dense 128B line: 64 batches fp16)
    unsigned int hraw = __ldg(g2 + sm_off[w][0] + l);
    float        wt   = sm_w[w][0];

    for (int s = 0; s < NS; ++s) {
        // issue next sensor's gather early (overlaps exchange+stores)
        unsigned int hn = 0; float wn = 0.0f;
        if (s + 1 < NS) {
            hn = __ldg(g2 + sm_off[w][s + 1] + l);
            wn = sm_w[w][s + 1];
        }

        __half2 hh = *reinterpret_cast<__half2*>(&hraw);
        float2  v  = __half22float2(hh);
        v.x *= wt; v.y *= wt;
        acc.x += v.x; acc.y += v.y;

        const int p = s & 1;
        ex[p][0][w][l] = v.x;               // batch 2l   of pixel w
        ex[p][1][w][l] = v.y;               // batch 2l+1 of pixel w
        __syncthreads();                    // single barrier (double-buffered)

        // store role: batch 2w / 2w+1, pixel px0+l  (128B coalesced)
        const float ux = ex[p][0][l][w];
        const float uy = ex[p][1][l][w];
        const size_t o0 = ((size_t)(2 * w) * NS + s) * NPIX + px0 + l;
        __stcs(pi + o0, ux);
        __stcs(pi + o0 + (size_t)NS * NPIX, uy);

        hraw = hn; wt = wn;
    }

    // ---- das: exchange acc, relu, store, per-batch max ----
    __syncthreads();
    ex[0][0][w][l] = acc.x;
    ex[0][1][w][l] = acc.y;
    __syncthreads();
    float ax = fmaxf(ex[0][0][l][w], 0.0f);
    float ay = fmaxf(ex[0][1][l][w], 0.0f);
    __stcs(out + (size_t)(2 * w)     * NPIX + px0 + l, ax);
    __stcs(out + (size_t)(2 * w + 1) * NPIX + px0 + l, ay);

    #pragma unroll
    for (int off = 16; off > 0; off >>= 1) {
        ax = fmaxf(ax, __shfl_xor_sync(0xffffffffu, ax, off));
        ay = fmaxf(ay, __shfl_xor_sync(0xffffffffu, ay, off));
    }
    if (l == 0) {
        atomicMax(reinterpret_cast<int*>(&g_bmax[2 * w]),     __float_as_int(ax));
        atomicMax(reinterpret_cast<int*>(&g_bmax[2 * w + 1]), __float_as_int(ay));
    }
}

__global__ __launch_bounds__(256) void norm_kernel(float* __restrict__ out)
{
    int i = blockIdx.x * blockDim.x + threadIdx.x;
    float4* p = reinterpret_cast<float4*>(out);
    float4 v = p[i];
    int b = (i * 4) >> 14;
    float m = g_bmax[b];
    float r = (m > 1e-8f) ? (1.0f / m) : 1.0f;
    v.x *= r; v.y *= r; v.z *= r; v.w *= r;
    p[i] = v;
}

extern "C" void kernel_launch(void* const* d_in, const int* in_sizes, int n_in,
                              void* d_out, int out_size)
{
    const float* sino = (const float*)d_in[0];   // [64,1,64,2030]
    const float* wts  = (const float*)d_in[1];   // [128,128,64]
    const int*   tidx = (const int*)d_in[2];     // [128,128,64]
    float* out = (float*)d_out;

    transpose_kernel<<<SNT / 64, 512>>>(sino);          // 2030 blocks

    das_kernel<<<NPIX / 32, 1024>>>(wts, tidx, out);    // 512 blocks

    norm_kernel<<<(NB * NPIX / 4) / 256, 256>>>(out);
}